// round 7
// baseline (speedup 1.0000x reference)
#include <cuda_runtime.h>
#include <math.h>

#define NN 50000
#define EE 800000
#define IN_DIM 128
#define HD 128
#define HD2 64
#define OUT_DIM 1000
#define KHOPS 10
#define EPSV 1e-5f

// ---------------- scratch (device globals; no allocation allowed) ------------
__device__ float g_Y1[(size_t)NN * HD];    // pre-BN layer 1
__device__ float g_Y2[(size_t)NN * HD];    // pre-BN layer 2
__device__ float g_H1[(size_t)NN * HD];    // layer-1 output (residual identity)
__device__ float g_P[(size_t)NN * HD2];    // projected 64d hop ping
__device__ float g_PB[(size_t)NN * HD2];   // hop pong
__device__ float g_O64[(size_t)NN * HD2];  // softmax-weighted accumulator (64d)
__device__ float g_S1[HD], g_Q1[HD], g_S2[HD], g_Q2[HD], g_S3[HD2], g_Q3[HD2];
__device__ float g_w[KHOPS + 1];
__device__ int   g_deg[NN];
__device__ int   g_rowptr[NN + 1];
__device__ int   g_cursor[NN];
__device__ int   g_colidx[EE];

// ---------------- init: zero stats/degrees, softmax(att) ---------------------
__global__ void k_init(const float* __restrict__ att) {
    int t = blockIdx.x * blockDim.x + threadIdx.x;
    int stride = gridDim.x * blockDim.x;
    for (int i = t; i < NN; i += stride) g_deg[i] = 0;
    if (t < HD)  { g_S1[t] = 0.f; g_Q1[t] = 0.f; g_S2[t] = 0.f; g_Q2[t] = 0.f; }
    if (t < HD2) { g_S3[t] = 0.f; g_Q3[t] = 0.f; }
    if (t == 0) {
        float m = -1e30f;
        for (int i = 0; i <= KHOPS; i++) m = fmaxf(m, att[i]);
        float e[KHOPS + 1]; float s = 0.f;
        for (int i = 0; i <= KHOPS; i++) { e[i] = expf(att[i] - m); s += e[i]; }
        for (int i = 0; i <= KHOPS; i++) g_w[i] = e[i] / s;
    }
}

// ---------------- tiled GEMM: C = act(A)[M,K] @ B[K,Nc] (+bias) --------------
// BM=128, BN=64, BK=16, 256 threads, 8x4 register tile per thread (R4 config).
// Optional fused BN column stats on C (Sp/Qp != null).
// Optional fused BN+ReLU(+resid) applied to A on load (SA != null):
//   A_eff[r,k] = relu(A[r,k]*scale[k] + shift[k]) (+ residA[r,k])
__global__ __launch_bounds__(256)
void k_gemm(const float* __restrict__ A, const float* __restrict__ B,
            const float* __restrict__ bias, float* __restrict__ C,
            float* __restrict__ Sp, float* __restrict__ Qp,
            const float* __restrict__ gA, const float* __restrict__ beA,
            const float* __restrict__ SA, const float* __restrict__ QA,
            const float* __restrict__ residA,
            int M, int Nc, int K) {
    __shared__ float As[128][17];
    __shared__ float Bs[16][68];
    __shared__ float cS[64], cQ[64];
    __shared__ float aSc[128], aSh[128];
    int tid = threadIdx.x;
    int tx = tid & 15;
    int ty = tid >> 4;
    int rowBase = blockIdx.y * 128;
    int colBase = blockIdx.x * 64;
    float acc[8][4] = {};

    if (Sp && tid < 64) { cS[tid] = 0.f; cQ[tid] = 0.f; }
    if (SA) {
        if (tid < K) {
            float mean = SA[tid] / (float)M;
            float var = QA[tid] / (float)M - mean * mean;
            float rstd = rsqrtf(var + EPSV);
            float scale = gA[tid] * rstd;
            aSc[tid] = scale;
            aSh[tid] = beA[tid] - mean * scale;
        }
        __syncthreads();
    }

    for (int k0 = 0; k0 < K; k0 += 16) {
        // A tile: 128 rows x 16 k = 512 float4, 2 per thread
        #pragma unroll
        for (int l = 0; l < 2; l++) {
            int f = tid + l * 256;
            int r = f >> 2, c = (f & 3) * 4;
            int gr = rowBase + r;
            float4 v = make_float4(0.f, 0.f, 0.f, 0.f);
            if (gr < M) {
                v = *(const float4*)(A + (size_t)gr * K + k0 + c);
                if (SA) {
                    int kc = k0 + c;
                    v.x = fmaxf(fmaf(v.x, aSc[kc + 0], aSh[kc + 0]), 0.f);
                    v.y = fmaxf(fmaf(v.y, aSc[kc + 1], aSh[kc + 1]), 0.f);
                    v.z = fmaxf(fmaf(v.z, aSc[kc + 2], aSh[kc + 2]), 0.f);
                    v.w = fmaxf(fmaf(v.w, aSc[kc + 3], aSh[kc + 3]), 0.f);
                    if (residA) {
                        float4 rr = *(const float4*)(residA + (size_t)gr * K + k0 + c);
                        v.x += rr.x; v.y += rr.y; v.z += rr.z; v.w += rr.w;
                    }
                }
            }
            As[r][c] = v.x; As[r][c + 1] = v.y; As[r][c + 2] = v.z; As[r][c + 3] = v.w;
        }
        {   // B tile: 16 k x 64 cols = 256 float4, 1 per thread
            int r = tid >> 4, c = (tid & 15) * 4;
            int gc = colBase + c;
            float4 v = make_float4(0.f, 0.f, 0.f, 0.f);
            if (gc < Nc) v = *(const float4*)(B + (size_t)(k0 + r) * Nc + gc);
            Bs[r][c] = v.x; Bs[r][c + 1] = v.y; Bs[r][c + 2] = v.z; Bs[r][c + 3] = v.w;
        }
        __syncthreads();
        #pragma unroll
        for (int kk = 0; kk < 16; kk++) {
            float4 bv = *(const float4*)&Bs[kk][tx * 4];
            float a[8];
            #pragma unroll
            for (int i = 0; i < 8; i++) a[i] = As[ty * 8 + i][kk];
            #pragma unroll
            for (int i = 0; i < 8; i++) {
                acc[i][0] = fmaf(a[i], bv.x, acc[i][0]);
                acc[i][1] = fmaf(a[i], bv.y, acc[i][1]);
                acc[i][2] = fmaf(a[i], bv.z, acc[i][2]);
                acc[i][3] = fmaf(a[i], bv.w, acc[i][3]);
            }
        }
        __syncthreads();
    }
    #pragma unroll
    for (int i = 0; i < 8; i++) {
        int r = rowBase + ty * 8 + i;
        if (r >= M) continue;
        #pragma unroll
        for (int j = 0; j < 4; j++) {
            int c = colBase + tx * 4 + j;
            if (c < Nc) {
                float v = acc[i][j];
                if (bias) v += bias[c];
                C[(size_t)r * Nc + c] = v;
            }
        }
    }
    if (Sp) {
        float s[4] = {0.f, 0.f, 0.f, 0.f};
        float q[4] = {0.f, 0.f, 0.f, 0.f};
        #pragma unroll
        for (int i = 0; i < 8; i++) {
            int r = rowBase + ty * 8 + i;
            if (r >= M) continue;
            #pragma unroll
            for (int j = 0; j < 4; j++) {
                float v = acc[i][j];
                s[j] += v; q[j] += v * v;
            }
        }
        #pragma unroll
        for (int j = 0; j < 4; j++) {
            atomicAdd(&cS[tx * 4 + j], s[j]);
            atomicAdd(&cQ[tx * 4 + j], q[j]);
        }
        __syncthreads();
        if (tid < 64) {
            int c = colBase + tid;
            if (c < Nc) {
                atomicAdd(Sp + c, cS[tid]);
                atomicAdd(Qp + c, cQ[tid]);
            }
        }
    }
}

// ---------------- BN apply + ReLU, vectorized float4 (layer 1 only) ----------
__global__ __launch_bounds__(256)
void k_apply(const float* __restrict__ Y, const float* __restrict__ g,
             const float* __restrict__ be, const float* __restrict__ S,
             const float* __restrict__ Q, float* __restrict__ H,
             int M, int C) {
    __shared__ float4 sc4[32], sh4[32];
    int tid = threadIdx.x;
    int c4 = C >> 2;
    if (tid < c4) {
        float4 s4, h4;
        float* sp = (float*)&s4;
        float* hp = (float*)&h4;
        #pragma unroll
        for (int k = 0; k < 4; k++) {
            int col = tid * 4 + k;
            float mean = S[col] / (float)M;
            float var = Q[col] / (float)M - mean * mean;
            float rstd = rsqrtf(var + EPSV);
            float scale = g[col] * rstd;
            sp[k] = scale;
            hp[k] = be[col] - mean * scale;
        }
        sc4[tid] = s4; sh4[tid] = h4;
    }
    __syncthreads();
    int total = M * c4;
    int stride = gridDim.x * blockDim.x;
    int mask = c4 - 1;
    for (int idx = blockIdx.x * blockDim.x + tid; idx < total; idx += stride) {
        int j4 = idx & mask;
        float4 y = ((const float4*)Y)[idx];
        float4 sc = sc4[j4], sh = sh4[j4];
        float4 r;
        r.x = fmaxf(fmaf(y.x, sc.x, sh.x), 0.f);
        r.y = fmaxf(fmaf(y.y, sc.y, sh.y), 0.f);
        r.z = fmaxf(fmaf(y.z, sc.z, sh.z), 0.f);
        r.w = fmaxf(fmaf(y.w, sc.w, sh.w), 0.f);
        ((float4*)H)[idx] = r;
    }
}

// ---------------- column stats for O64 (final BN) ----------------------------
__global__ __launch_bounds__(256)
void k_stats64(const float* __restrict__ Y, float* __restrict__ S,
               float* __restrict__ Q, int M) {
    int col = threadIdx.x & 63;
    int rg = threadIdx.x >> 6;  // 0..3
    float s = 0.f, q = 0.f;
    for (int r = blockIdx.x * 4 + rg; r < M; r += gridDim.x * 4) {
        float v = Y[(size_t)r * HD2 + col];
        s += v; q += v * v;
    }
    atomicAdd(S + col, s);
    atomicAdd(Q + col, q);
}

// ---------------- CSR build: histogram -> scan -> scatter --------------------
__global__ void k_hist(const int* __restrict__ dst) {
    int t = blockIdx.x * blockDim.x + threadIdx.x;
    int stride = gridDim.x * blockDim.x;
    for (int e = t; e < EE; e += stride) atomicAdd(&g_deg[dst[e]], 1);
}

__global__ void k_scan() {  // one block, 1024 threads
    __shared__ int ss[1024];
    int t = threadIdx.x;
    const int CH = (NN + 1023) / 1024;
    int lo = t * CH;
    int hi = lo + CH; if (hi > NN) hi = NN;
    int loc = 0;
    for (int i = lo; i < hi; i++) loc += g_deg[i];
    ss[t] = loc;
    __syncthreads();
    for (int off = 1; off < 1024; off <<= 1) {
        int v = (t >= off) ? ss[t - off] : 0;
        __syncthreads();
        ss[t] += v;
        __syncthreads();
    }
    int run = ss[t] - loc;  // exclusive prefix
    for (int i = lo; i < hi; i++) {
        g_rowptr[i] = run;
        g_cursor[i] = run;
        run += g_deg[i];
    }
    if (t == 1023) g_rowptr[NN] = ss[1023];
}

__global__ void k_scatter(const int* __restrict__ src, const int* __restrict__ dst) {
    int t = blockIdx.x * blockDim.x + threadIdx.x;
    int stride = gridDim.x * blockDim.x;
    for (int e = t; e < EE; e += stride) {
        int d = dst[e];
        int p = atomicAdd(&g_cursor[d], 1);
        g_colidx[p] = src[e];
    }
}

// ---------------- 64d propagation hop: half-warp-per-dst gather-reduce -------
// nxt[d] = sum_{in-edges} cur[src];  O64[d] = (hop==0 ? w0*cur[d] : O64[d]) + w[hop+1]*nxt[d]
__global__ __launch_bounds__(256)
void k_hop64(int hop) {
    const float* __restrict__ cur = (hop & 1) ? g_PB : g_P;
    float* __restrict__ nxt       = (hop & 1) ? g_P : g_PB;
    int gid = blockIdx.x * blockDim.x + threadIdx.x;
    int d = gid >> 4;            // half-warp per destination node
    int lane = threadIdx.x & 15;
    if (d >= NN) return;
    float w = g_w[hop + 1];
    int s = g_rowptr[d];
    int e = g_rowptr[d + 1];
    float4 acc0 = make_float4(0.f, 0.f, 0.f, 0.f);
    float4 acc1 = make_float4(0.f, 0.f, 0.f, 0.f);
    float4 acc2 = make_float4(0.f, 0.f, 0.f, 0.f);
    float4 acc3 = make_float4(0.f, 0.f, 0.f, 0.f);
    int i = s;
    for (; i + 3 < e; i += 4) {
        int s0 = __ldg(&g_colidx[i]);
        int s1 = __ldg(&g_colidx[i + 1]);
        int s2 = __ldg(&g_colidx[i + 2]);
        int s3 = __ldg(&g_colidx[i + 3]);
        float4 v0 = *(const float4*)(cur + (size_t)s0 * HD2 + lane * 4);
        float4 v1 = *(const float4*)(cur + (size_t)s1 * HD2 + lane * 4);
        float4 v2 = *(const float4*)(cur + (size_t)s2 * HD2 + lane * 4);
        float4 v3 = *(const float4*)(cur + (size_t)s3 * HD2 + lane * 4);
        acc0.x += v0.x; acc0.y += v0.y; acc0.z += v0.z; acc0.w += v0.w;
        acc1.x += v1.x; acc1.y += v1.y; acc1.z += v1.z; acc1.w += v1.w;
        acc2.x += v2.x; acc2.y += v2.y; acc2.z += v2.z; acc2.w += v2.w;
        acc3.x += v3.x; acc3.y += v3.y; acc3.z += v3.z; acc3.w += v3.w;
    }
    for (; i < e; i++) {
        int s0 = __ldg(&g_colidx[i]);
        float4 v0 = *(const float4*)(cur + (size_t)s0 * HD2 + lane * 4);
        acc0.x += v0.x; acc0.y += v0.y; acc0.z += v0.z; acc0.w += v0.w;
    }
    float4 a = make_float4((acc0.x + acc1.x) + (acc2.x + acc3.x),
                           (acc0.y + acc1.y) + (acc2.y + acc3.y),
                           (acc0.z + acc1.z) + (acc2.z + acc3.z),
                           (acc0.w + acc1.w) + (acc2.w + acc3.w));
    size_t base = (size_t)d * HD2 + lane * 4;
    *(float4*)(nxt + base) = a;
    float4 o;
    if (hop == 0) {
        float w0 = g_w[0];
        float4 c = *(const float4*)(cur + base);
        o = make_float4(w0 * c.x, w0 * c.y, w0 * c.z, w0 * c.w);
    } else {
        o = *(float4*)(g_O64 + base);
    }
    o.x += w * a.x; o.y += w * a.y; o.z += w * a.z; o.w += w * a.w;
    *(float4*)(g_O64 + base) = o;
}

// ---------------- host launcher ----------------------------------------------
extern "C" void kernel_launch(void* const* d_in, const int* in_sizes, int n_in,
                              void* d_out, int out_size) {
    const float* x    = (const float*)d_in[0];
    const int*   ei   = (const int*)d_in[1];
    const float* W1   = (const float*)d_in[2];
    const float* g1   = (const float*)d_in[4];
    const float* be1  = (const float*)d_in[5];
    const float* W2   = (const float*)d_in[6];
    const float* g2   = (const float*)d_in[8];
    const float* be2  = (const float*)d_in[9];
    const float* att  = (const float*)d_in[10];
    const float* W3   = (const float*)d_in[11];
    const float* g3   = (const float*)d_in[13];
    const float* be3  = (const float*)d_in[14];
    const float* Wout = (const float*)d_in[15];
    const float* bout = (const float*)d_in[16];
    // b1/b2/b3 dropped: BN is invariant to per-column constant shifts.
    const int* srcp = ei;
    const int* dstp = ei + EE;
    float* out = (float*)d_out;

    float *Y1, *Y2, *H1, *P, *O64, *S1, *Q1, *S2, *Q2, *S3, *Q3;
    cudaGetSymbolAddress((void**)&Y1,  g_Y1);
    cudaGetSymbolAddress((void**)&Y2,  g_Y2);
    cudaGetSymbolAddress((void**)&H1,  g_H1);
    cudaGetSymbolAddress((void**)&P,   g_P);
    cudaGetSymbolAddress((void**)&O64, g_O64);
    cudaGetSymbolAddress((void**)&S1,  g_S1);
    cudaGetSymbolAddress((void**)&Q1,  g_Q1);
    cudaGetSymbolAddress((void**)&S2,  g_S2);
    cudaGetSymbolAddress((void**)&Q2,  g_Q2);
    cudaGetSymbolAddress((void**)&S3,  g_S3);
    cudaGetSymbolAddress((void**)&Q3,  g_Q3);

    const int MB = (NN + 127) / 128;  // 391 row-tiles

    k_init<<<200, 256>>>(att);

    // CSR by destination (independent of MLP; do it early)
    k_hist<<<1024, 256>>>(dstp);
    k_scan<<<1, 1024>>>();
    k_scatter<<<1024, 256>>>(srcp, dstp);

    // layer 1: Y1 = x @ W1 (stats fused); H1 = relu(bn1(Y1))
    k_gemm<<<dim3(2, MB), 256>>>(x, W1, nullptr, Y1, S1, Q1,
                                 nullptr, nullptr, nullptr, nullptr, nullptr,
                                 NN, HD, IN_DIM);
    k_apply<<<2048, 256>>>(Y1, g1, be1, S1, Q1, H1, NN, HD);

    // layer 2: Y2 = H1 @ W2 (stats fused)
    k_gemm<<<dim3(2, MB), 256>>>(H1, W2, nullptr, Y2, S2, Q2,
                                 nullptr, nullptr, nullptr, nullptr, nullptr,
                                 NN, HD, HD);

    // projection with fused apply: P = (relu(bn2(Y2)) + H1) @ W3
    k_gemm<<<dim3(1, MB), 256>>>(Y2, W3, nullptr, P, nullptr, nullptr,
                                 g2, be2, S2, Q2, H1,
                                 NN, HD2, HD);

    // K hops in 64d; weighted accumulation fused (hop 0 seeds O64 = w0*P)
    for (int h = 0; h < KHOPS; h++)
        k_hop64<<<(NN * 16 + 255) / 256, 256>>>(h);

    // output with fused apply: out = relu(bn3(O64)) @ Wout + bout
    k_stats64<<<1024, 256>>>(O64, S3, Q3, NN);
    k_gemm<<<dim3((OUT_DIM + 63) / 64, MB), 256>>>(O64, Wout, bout, out,
                                                   nullptr, nullptr,
                                                   g3, be3, S3, Q3, nullptr,
                                                   NN, OUT_DIM, HD2);
}

// round 9
// speedup vs baseline: 1.5900x; 1.5900x over previous
#include <cuda_runtime.h>
#include <math.h>

#define NN 50000
#define EE 800000
#define IN_DIM 128
#define HD 128
#define HD2 64
#define OUT_DIM 1000
#define KHOPS 10
#define EPSV 1e-5f

// ---------------- scratch (device globals; no allocation allowed) ------------
__device__ float g_Y1[(size_t)NN * HD];    // pre-BN layer 1
__device__ float g_Y2[(size_t)NN * HD];    // pre-BN layer 2
__device__ float g_H1[(size_t)NN * HD];    // layer-1 output (residual identity)
__device__ float g_P[(size_t)NN * HD2];    // projected 64d hop ping
__device__ float g_PB[(size_t)NN * HD2];   // hop pong
__device__ float g_O64[(size_t)NN * HD2];  // softmax-weighted accumulator (64d)
__device__ float g_S1[HD], g_Q1[HD], g_S2[HD], g_Q2[HD], g_S3[HD2], g_Q3[HD2];
__device__ float g_w[KHOPS + 1];
__device__ int   g_deg[NN];
__device__ int   g_rowptr[NN + 1];
__device__ int   g_cursor[NN];
__device__ int   g_colidx[EE];

// ---------------- init: zero stats/degrees, softmax(att) ---------------------
__global__ void k_init(const float* __restrict__ att) {
    int t = blockIdx.x * blockDim.x + threadIdx.x;
    int stride = gridDim.x * blockDim.x;
    for (int i = t; i < NN; i += stride) g_deg[i] = 0;
    if (t < HD)  { g_S1[t] = 0.f; g_Q1[t] = 0.f; g_S2[t] = 0.f; g_Q2[t] = 0.f; }
    if (t < HD2) { g_S3[t] = 0.f; g_Q3[t] = 0.f; }
    if (t == 0) {
        float m = -1e30f;
        for (int i = 0; i <= KHOPS; i++) m = fmaxf(m, att[i]);
        float e[KHOPS + 1]; float s = 0.f;
        for (int i = 0; i <= KHOPS; i++) { e[i] = expf(att[i] - m); s += e[i]; }
        for (int i = 0; i <= KHOPS; i++) g_w[i] = e[i] / s;
    }
}

// ---------------- tiled GEMM: C = act(A)[M,K] @ B[K,Nc] (+bias) --------------
// BM=128, BN=64, BK=16, 256 threads, 8x4 register tile (proven R4 config).
// Templated so each call site compiles a lean specialization:
//   STATS : fused BN column stats on C (Sp/Qp).
//   FUSEA : A_eff[r,k] = relu(A[r,k]*scale[k] + shift[k])
//   RESID : (+ residA[r,k]) after the fused activation.
// __launch_bounds__(256, 2) caps regs so >=2 CTAs/SM are guaranteed.
template<bool FUSEA, bool RESID, bool STATS>
__global__ __launch_bounds__(256, 2)
void k_gemm(const float* __restrict__ A, const float* __restrict__ B,
            const float* __restrict__ bias, float* __restrict__ C,
            float* __restrict__ Sp, float* __restrict__ Qp,
            const float* __restrict__ gA, const float* __restrict__ beA,
            const float* __restrict__ SA, const float* __restrict__ QA,
            const float* __restrict__ residA,
            int M, int Nc, int K) {
    __shared__ float As[128][17];
    __shared__ float Bs[16][68];
    __shared__ float cS[64], cQ[64];
    __shared__ float aSc[128], aSh[128];
    int tid = threadIdx.x;
    int tx = tid & 15;
    int ty = tid >> 4;
    int rowBase = blockIdx.y * 128;
    int colBase = blockIdx.x * 64;
    float acc[8][4] = {};

    if (STATS && tid < 64) { cS[tid] = 0.f; cQ[tid] = 0.f; }
    if (FUSEA) {
        if (tid < K) {
            float mean = SA[tid] / (float)M;
            float var = QA[tid] / (float)M - mean * mean;
            float rstd = rsqrtf(var + EPSV);
            float scale = gA[tid] * rstd;
            aSc[tid] = scale;
            aSh[tid] = beA[tid] - mean * scale;
        }
        __syncthreads();
    }

    for (int k0 = 0; k0 < K; k0 += 16) {
        // A tile: 128 rows x 16 k = 512 float4, 2 per thread
        #pragma unroll
        for (int l = 0; l < 2; l++) {
            int f = tid + l * 256;
            int r = f >> 2, c = (f & 3) * 4;
            int gr = rowBase + r;
            float4 v = make_float4(0.f, 0.f, 0.f, 0.f);
            if (gr < M) {
                v = *(const float4*)(A + (size_t)gr * K + k0 + c);
                if (FUSEA) {
                    int kc = k0 + c;
                    v.x = fmaxf(fmaf(v.x, aSc[kc + 0], aSh[kc + 0]), 0.f);
                    v.y = fmaxf(fmaf(v.y, aSc[kc + 1], aSh[kc + 1]), 0.f);
                    v.z = fmaxf(fmaf(v.z, aSc[kc + 2], aSh[kc + 2]), 0.f);
                    v.w = fmaxf(fmaf(v.w, aSc[kc + 3], aSh[kc + 3]), 0.f);
                    if (RESID) {
                        float4 rr = *(const float4*)(residA + (size_t)gr * K + k0 + c);
                        v.x += rr.x; v.y += rr.y; v.z += rr.z; v.w += rr.w;
                    }
                }
            }
            As[r][c] = v.x; As[r][c + 1] = v.y; As[r][c + 2] = v.z; As[r][c + 3] = v.w;
        }
        {   // B tile: 16 k x 64 cols = 256 float4, 1 per thread
            int r = tid >> 4, c = (tid & 15) * 4;
            int gc = colBase + c;
            float4 v = make_float4(0.f, 0.f, 0.f, 0.f);
            if (gc < Nc) v = *(const float4*)(B + (size_t)(k0 + r) * Nc + gc);
            Bs[r][c] = v.x; Bs[r][c + 1] = v.y; Bs[r][c + 2] = v.z; Bs[r][c + 3] = v.w;
        }
        __syncthreads();
        #pragma unroll
        for (int kk = 0; kk < 16; kk++) {
            float4 bv = *(const float4*)&Bs[kk][tx * 4];
            float a[8];
            #pragma unroll
            for (int i = 0; i < 8; i++) a[i] = As[ty * 8 + i][kk];
            #pragma unroll
            for (int i = 0; i < 8; i++) {
                acc[i][0] = fmaf(a[i], bv.x, acc[i][0]);
                acc[i][1] = fmaf(a[i], bv.y, acc[i][1]);
                acc[i][2] = fmaf(a[i], bv.z, acc[i][2]);
                acc[i][3] = fmaf(a[i], bv.w, acc[i][3]);
            }
        }
        __syncthreads();
    }
    #pragma unroll
    for (int i = 0; i < 8; i++) {
        int r = rowBase + ty * 8 + i;
        if (r >= M) continue;
        #pragma unroll
        for (int j = 0; j < 4; j++) {
            int c = colBase + tx * 4 + j;
            if (c < Nc) {
                float v = acc[i][j];
                if (bias) v += bias[c];
                C[(size_t)r * Nc + c] = v;
            }
        }
    }
    if (STATS) {
        float s[4] = {0.f, 0.f, 0.f, 0.f};
        float q[4] = {0.f, 0.f, 0.f, 0.f};
        #pragma unroll
        for (int i = 0; i < 8; i++) {
            int r = rowBase + ty * 8 + i;
            if (r >= M) continue;
            #pragma unroll
            for (int j = 0; j < 4; j++) {
                float v = acc[i][j];
                s[j] += v; q[j] += v * v;
            }
        }
        #pragma unroll
        for (int j = 0; j < 4; j++) {
            atomicAdd(&cS[tx * 4 + j], s[j]);
            atomicAdd(&cQ[tx * 4 + j], q[j]);
        }
        __syncthreads();
        if (tid < 64) {
            int c = colBase + tid;
            if (c < Nc) {
                atomicAdd(Sp + c, cS[tid]);
                atomicAdd(Qp + c, cQ[tid]);
            }
        }
    }
}

// ---------------- BN apply + ReLU, vectorized float4 (layer 1 only) ----------
__global__ __launch_bounds__(256)
void k_apply(const float* __restrict__ Y, const float* __restrict__ g,
             const float* __restrict__ be, const float* __restrict__ S,
             const float* __restrict__ Q, float* __restrict__ H,
             int M, int C) {
    __shared__ float4 sc4[32], sh4[32];
    int tid = threadIdx.x;
    int c4 = C >> 2;
    if (tid < c4) {
        float4 s4, h4;
        float* sp = (float*)&s4;
        float* hp = (float*)&h4;
        #pragma unroll
        for (int k = 0; k < 4; k++) {
            int col = tid * 4 + k;
            float mean = S[col] / (float)M;
            float var = Q[col] / (float)M - mean * mean;
            float rstd = rsqrtf(var + EPSV);
            float scale = g[col] * rstd;
            sp[k] = scale;
            hp[k] = be[col] - mean * scale;
        }
        sc4[tid] = s4; sh4[tid] = h4;
    }
    __syncthreads();
    int total = M * c4;
    int stride = gridDim.x * blockDim.x;
    int mask = c4 - 1;
    for (int idx = blockIdx.x * blockDim.x + tid; idx < total; idx += stride) {
        int j4 = idx & mask;
        float4 y = ((const float4*)Y)[idx];
        float4 sc = sc4[j4], sh = sh4[j4];
        float4 r;
        r.x = fmaxf(fmaf(y.x, sc.x, sh.x), 0.f);
        r.y = fmaxf(fmaf(y.y, sc.y, sh.y), 0.f);
        r.z = fmaxf(fmaf(y.z, sc.z, sh.z), 0.f);
        r.w = fmaxf(fmaf(y.w, sc.w, sh.w), 0.f);
        ((float4*)H)[idx] = r;
    }
}

// ---------------- column stats for O64 (final BN) ----------------------------
__global__ __launch_bounds__(256)
void k_stats64(const float* __restrict__ Y, float* __restrict__ S,
               float* __restrict__ Q, int M) {
    int col = threadIdx.x & 63;
    int rg = threadIdx.x >> 6;  // 0..3
    float s = 0.f, q = 0.f;
    for (int r = blockIdx.x * 4 + rg; r < M; r += gridDim.x * 4) {
        float v = Y[(size_t)r * HD2 + col];
        s += v; q += v * v;
    }
    atomicAdd(S + col, s);
    atomicAdd(Q + col, q);
}

// ---------------- CSR build: histogram -> scan -> scatter --------------------
__global__ void k_hist(const int* __restrict__ dst) {
    int t = blockIdx.x * blockDim.x + threadIdx.x;
    int stride = gridDim.x * blockDim.x;
    for (int e = t; e < EE; e += stride) atomicAdd(&g_deg[dst[e]], 1);
}

__global__ void k_scan() {  // one block, 1024 threads
    __shared__ int ss[1024];
    int t = threadIdx.x;
    const int CH = (NN + 1023) / 1024;
    int lo = t * CH;
    int hi = lo + CH; if (hi > NN) hi = NN;
    int loc = 0;
    for (int i = lo; i < hi; i++) loc += g_deg[i];
    ss[t] = loc;
    __syncthreads();
    for (int off = 1; off < 1024; off <<= 1) {
        int v = (t >= off) ? ss[t - off] : 0;
        __syncthreads();
        ss[t] += v;
        __syncthreads();
    }
    int run = ss[t] - loc;  // exclusive prefix
    for (int i = lo; i < hi; i++) {
        g_rowptr[i] = run;
        g_cursor[i] = run;
        run += g_deg[i];
    }
    if (t == 1023) g_rowptr[NN] = ss[1023];
}

__global__ void k_scatter(const int* __restrict__ src, const int* __restrict__ dst) {
    int t = blockIdx.x * blockDim.x + threadIdx.x;
    int stride = gridDim.x * blockDim.x;
    for (int e = t; e < EE; e += stride) {
        int d = dst[e];
        int p = atomicAdd(&g_cursor[d], 1);
        g_colidx[p] = src[e];
    }
}

// ---------------- 64d propagation hop: half-warp-per-dst gather-reduce -------
// nxt[d] = sum_{in-edges} cur[src];  O64[d] = (hop==0 ? w0*cur[d] : O64[d]) + w[hop+1]*nxt[d]
__global__ __launch_bounds__(256)
void k_hop64(int hop) {
    const float* __restrict__ cur = (hop & 1) ? g_PB : g_P;
    float* __restrict__ nxt       = (hop & 1) ? g_P : g_PB;
    int gid = blockIdx.x * blockDim.x + threadIdx.x;
    int d = gid >> 4;            // half-warp per destination node
    int lane = threadIdx.x & 15;
    if (d >= NN) return;
    float w = g_w[hop + 1];
    int s = g_rowptr[d];
    int e = g_rowptr[d + 1];
    float4 acc0 = make_float4(0.f, 0.f, 0.f, 0.f);
    float4 acc1 = make_float4(0.f, 0.f, 0.f, 0.f);
    float4 acc2 = make_float4(0.f, 0.f, 0.f, 0.f);
    float4 acc3 = make_float4(0.f, 0.f, 0.f, 0.f);
    int i = s;
    for (; i + 3 < e; i += 4) {
        int s0 = __ldg(&g_colidx[i]);
        int s1 = __ldg(&g_colidx[i + 1]);
        int s2 = __ldg(&g_colidx[i + 2]);
        int s3 = __ldg(&g_colidx[i + 3]);
        float4 v0 = *(const float4*)(cur + (size_t)s0 * HD2 + lane * 4);
        float4 v1 = *(const float4*)(cur + (size_t)s1 * HD2 + lane * 4);
        float4 v2 = *(const float4*)(cur + (size_t)s2 * HD2 + lane * 4);
        float4 v3 = *(const float4*)(cur + (size_t)s3 * HD2 + lane * 4);
        acc0.x += v0.x; acc0.y += v0.y; acc0.z += v0.z; acc0.w += v0.w;
        acc1.x += v1.x; acc1.y += v1.y; acc1.z += v1.z; acc1.w += v1.w;
        acc2.x += v2.x; acc2.y += v2.y; acc2.z += v2.z; acc2.w += v2.w;
        acc3.x += v3.x; acc3.y += v3.y; acc3.z += v3.z; acc3.w += v3.w;
    }
    for (; i < e; i++) {
        int s0 = __ldg(&g_colidx[i]);
        float4 v0 = *(const float4*)(cur + (size_t)s0 * HD2 + lane * 4);
        acc0.x += v0.x; acc0.y += v0.y; acc0.z += v0.z; acc0.w += v0.w;
    }
    float4 a = make_float4((acc0.x + acc1.x) + (acc2.x + acc3.x),
                           (acc0.y + acc1.y) + (acc2.y + acc3.y),
                           (acc0.z + acc1.z) + (acc2.z + acc3.z),
                           (acc0.w + acc1.w) + (acc2.w + acc3.w));
    size_t base = (size_t)d * HD2 + lane * 4;
    *(float4*)(nxt + base) = a;
    float4 o;
    if (hop == 0) {
        float w0 = g_w[0];
        float4 c = *(const float4*)(cur + base);
        o = make_float4(w0 * c.x, w0 * c.y, w0 * c.z, w0 * c.w);
    } else {
        o = *(float4*)(g_O64 + base);
    }
    o.x += w * a.x; o.y += w * a.y; o.z += w * a.z; o.w += w * a.w;
    *(float4*)(g_O64 + base) = o;
}

// ---------------- host launcher ----------------------------------------------
extern "C" void kernel_launch(void* const* d_in, const int* in_sizes, int n_in,
                              void* d_out, int out_size) {
    const float* x    = (const float*)d_in[0];
    const int*   ei   = (const int*)d_in[1];
    const float* W1   = (const float*)d_in[2];
    const float* g1   = (const float*)d_in[4];
    const float* be1  = (const float*)d_in[5];
    const float* W2   = (const float*)d_in[6];
    const float* g2   = (const float*)d_in[8];
    const float* be2  = (const float*)d_in[9];
    const float* att  = (const float*)d_in[10];
    const float* W3   = (const float*)d_in[11];
    const float* g3   = (const float*)d_in[13];
    const float* be3  = (const float*)d_in[14];
    const float* Wout = (const float*)d_in[15];
    const float* bout = (const float*)d_in[16];
    // b1/b2/b3 dropped: BN is invariant to per-column constant shifts.
    const int* srcp = ei;
    const int* dstp = ei + EE;
    float* out = (float*)d_out;

    float *Y1, *Y2, *H1, *P, *O64, *S1, *Q1, *S2, *Q2, *S3, *Q3;
    cudaGetSymbolAddress((void**)&Y1,  g_Y1);
    cudaGetSymbolAddress((void**)&Y2,  g_Y2);
    cudaGetSymbolAddress((void**)&H1,  g_H1);
    cudaGetSymbolAddress((void**)&P,   g_P);
    cudaGetSymbolAddress((void**)&O64, g_O64);
    cudaGetSymbolAddress((void**)&S1,  g_S1);
    cudaGetSymbolAddress((void**)&Q1,  g_Q1);
    cudaGetSymbolAddress((void**)&S2,  g_S2);
    cudaGetSymbolAddress((void**)&Q2,  g_Q2);
    cudaGetSymbolAddress((void**)&S3,  g_S3);
    cudaGetSymbolAddress((void**)&Q3,  g_Q3);

    const int MB = (NN + 127) / 128;  // 391 row-tiles

    k_init<<<200, 256>>>(att);

    // CSR by destination (independent of MLP; do it early)
    k_hist<<<1024, 256>>>(dstp);
    k_scan<<<1, 1024>>>();
    k_scatter<<<1024, 256>>>(srcp, dstp);

    // layer 1: Y1 = x @ W1 (stats fused); H1 = relu(bn1(Y1))
    k_gemm<false, false, true><<<dim3(2, MB), 256>>>(
        x, W1, nullptr, Y1, S1, Q1,
        nullptr, nullptr, nullptr, nullptr, nullptr, NN, HD, IN_DIM);
    k_apply<<<2048, 256>>>(Y1, g1, be1, S1, Q1, H1, NN, HD);

    // layer 2: Y2 = H1 @ W2 (stats fused)
    k_gemm<false, false, true><<<dim3(2, MB), 256>>>(
        H1, W2, nullptr, Y2, S2, Q2,
        nullptr, nullptr, nullptr, nullptr, nullptr, NN, HD, HD);

    // projection with fused apply: P = (relu(bn2(Y2)) + H1) @ W3
    k_gemm<true, true, false><<<dim3(1, MB), 256>>>(
        Y2, W3, nullptr, P, nullptr, nullptr,
        g2, be2, S2, Q2, H1, NN, HD2, HD);

    // K hops in 64d; weighted accumulation fused (hop 0 seeds O64 = w0*P)
    for (int h = 0; h < KHOPS; h++)
        k_hop64<<<(NN * 16 + 255) / 256, 256>>>(h);

    // output with fused apply: out = relu(bn3(O64)) @ Wout + bout
    k_stats64<<<1024, 256>>>(O64, S3, Q3, NN);
    k_gemm<true, false, false><<<dim3((OUT_DIM + 63) / 64, MB), 256>>>(
        O64, Wout, bout, out, nullptr, nullptr,
        g3, be3, S3, Q3, nullptr, NN, OUT_DIM, HD2);
}

// round 10
// speedup vs baseline: 1.9042x; 1.1976x over previous
#include <cuda_runtime.h>
#include <math.h>
#include <stdint.h>

#define NN 50000
#define EE 800000
#define IN_DIM 128
#define HD 128
#define HD2 64
#define OUT_DIM 1000
#define KHOPS 10
#define EPSV 1e-5f

// ---------------- scratch (device globals; no allocation allowed) ------------
__device__ float g_Y1[(size_t)NN * HD];    // pre-BN layer 1
__device__ float g_Y2[(size_t)NN * HD];    // pre-BN layer 2
__device__ float g_H1[(size_t)NN * HD];    // layer-1 output (residual identity)
__device__ float g_P[(size_t)NN * HD2];    // projected 64d hop ping
__device__ float g_PB[(size_t)NN * HD2];   // hop pong
__device__ float g_O64[(size_t)NN * HD2];  // softmax-weighted accumulator (64d)
__device__ float g_S1[HD], g_Q1[HD], g_S2[HD], g_Q2[HD], g_S3[HD2], g_Q3[HD2];
__device__ float g_w[KHOPS + 1];
__device__ int   g_deg[NN];
__device__ int   g_rowptr[NN + 1];
__device__ int   g_cursor[NN];
__device__ int   g_colidx[EE];

// ---------------- init: zero stats/degrees, softmax(att) ---------------------
__global__ void k_init(const float* __restrict__ att) {
    int t = blockIdx.x * blockDim.x + threadIdx.x;
    int stride = gridDim.x * blockDim.x;
    for (int i = t; i < NN; i += stride) g_deg[i] = 0;
    if (t < HD)  { g_S1[t] = 0.f; g_Q1[t] = 0.f; g_S2[t] = 0.f; g_Q2[t] = 0.f; }
    if (t < HD2) { g_S3[t] = 0.f; g_Q3[t] = 0.f; }
    if (t == 0) {
        float m = -1e30f;
        for (int i = 0; i <= KHOPS; i++) m = fmaxf(m, att[i]);
        float e[KHOPS + 1]; float s = 0.f;
        for (int i = 0; i <= KHOPS; i++) { e[i] = expf(att[i] - m); s += e[i]; }
        for (int i = 0; i <= KHOPS; i++) g_w[i] = e[i] / s;
    }
}

// ---------------- tiled GEMM: C = act(A)[M,K] @ B[K,Nc] (+bias) --------------
// BM=128, BN=64, BK=16, 256 threads, 8x4 register tile (proven R4 config).
template<bool FUSEA, bool RESID, bool STATS>
__global__ __launch_bounds__(256, 2)
void k_gemm(const float* __restrict__ A, const float* __restrict__ B,
            const float* __restrict__ bias, float* __restrict__ C,
            float* __restrict__ Sp, float* __restrict__ Qp,
            const float* __restrict__ gA, const float* __restrict__ beA,
            const float* __restrict__ SA, const float* __restrict__ QA,
            const float* __restrict__ residA,
            int M, int Nc, int K) {
    __shared__ float As[128][17];
    __shared__ float Bs[16][68];
    __shared__ float cS[64], cQ[64];
    __shared__ float aSc[128], aSh[128];
    int tid = threadIdx.x;
    int tx = tid & 15;
    int ty = tid >> 4;
    int rowBase = blockIdx.y * 128;
    int colBase = blockIdx.x * 64;
    float acc[8][4] = {};

    if (STATS && tid < 64) { cS[tid] = 0.f; cQ[tid] = 0.f; }
    if (FUSEA) {
        if (tid < K) {
            float mean = SA[tid] / (float)M;
            float var = QA[tid] / (float)M - mean * mean;
            float rstd = rsqrtf(var + EPSV);
            float scale = gA[tid] * rstd;
            aSc[tid] = scale;
            aSh[tid] = beA[tid] - mean * scale;
        }
        __syncthreads();
    }

    for (int k0 = 0; k0 < K; k0 += 16) {
        #pragma unroll
        for (int l = 0; l < 2; l++) {
            int f = tid + l * 256;
            int r = f >> 2, c = (f & 3) * 4;
            int gr = rowBase + r;
            float4 v = make_float4(0.f, 0.f, 0.f, 0.f);
            if (gr < M) {
                v = *(const float4*)(A + (size_t)gr * K + k0 + c);
                if (FUSEA) {
                    int kc = k0 + c;
                    v.x = fmaxf(fmaf(v.x, aSc[kc + 0], aSh[kc + 0]), 0.f);
                    v.y = fmaxf(fmaf(v.y, aSc[kc + 1], aSh[kc + 1]), 0.f);
                    v.z = fmaxf(fmaf(v.z, aSc[kc + 2], aSh[kc + 2]), 0.f);
                    v.w = fmaxf(fmaf(v.w, aSc[kc + 3], aSh[kc + 3]), 0.f);
                    if (RESID) {
                        float4 rr = *(const float4*)(residA + (size_t)gr * K + k0 + c);
                        v.x += rr.x; v.y += rr.y; v.z += rr.z; v.w += rr.w;
                    }
                }
            }
            As[r][c] = v.x; As[r][c + 1] = v.y; As[r][c + 2] = v.z; As[r][c + 3] = v.w;
        }
        {
            int r = tid >> 4, c = (tid & 15) * 4;
            int gc = colBase + c;
            float4 v = make_float4(0.f, 0.f, 0.f, 0.f);
            if (gc < Nc) v = *(const float4*)(B + (size_t)(k0 + r) * Nc + gc);
            Bs[r][c] = v.x; Bs[r][c + 1] = v.y; Bs[r][c + 2] = v.z; Bs[r][c + 3] = v.w;
        }
        __syncthreads();
        #pragma unroll
        for (int kk = 0; kk < 16; kk++) {
            float4 bv = *(const float4*)&Bs[kk][tx * 4];
            float a[8];
            #pragma unroll
            for (int i = 0; i < 8; i++) a[i] = As[ty * 8 + i][kk];
            #pragma unroll
            for (int i = 0; i < 8; i++) {
                acc[i][0] = fmaf(a[i], bv.x, acc[i][0]);
                acc[i][1] = fmaf(a[i], bv.y, acc[i][1]);
                acc[i][2] = fmaf(a[i], bv.z, acc[i][2]);
                acc[i][3] = fmaf(a[i], bv.w, acc[i][3]);
            }
        }
        __syncthreads();
    }
    #pragma unroll
    for (int i = 0; i < 8; i++) {
        int r = rowBase + ty * 8 + i;
        if (r >= M) continue;
        #pragma unroll
        for (int j = 0; j < 4; j++) {
            int c = colBase + tx * 4 + j;
            if (c < Nc) {
                float v = acc[i][j];
                if (bias) v += bias[c];
                C[(size_t)r * Nc + c] = v;
            }
        }
    }
    if (STATS) {
        float s[4] = {0.f, 0.f, 0.f, 0.f};
        float q[4] = {0.f, 0.f, 0.f, 0.f};
        #pragma unroll
        for (int i = 0; i < 8; i++) {
            int r = rowBase + ty * 8 + i;
            if (r >= M) continue;
            #pragma unroll
            for (int j = 0; j < 4; j++) {
                float v = acc[i][j];
                s[j] += v; q[j] += v * v;
            }
        }
        #pragma unroll
        for (int j = 0; j < 4; j++) {
            atomicAdd(&cS[tx * 4 + j], s[j]);
            atomicAdd(&cQ[tx * 4 + j], q[j]);
        }
        __syncthreads();
        if (tid < 64) {
            int c = colBase + tid;
            if (c < Nc) {
                atomicAdd(Sp + c, cS[tid]);
                atomicAdd(Qp + c, cQ[tid]);
            }
        }
    }
}

// ---------------- tf32 helpers -----------------------------------------------
__device__ __forceinline__ uint32_t f2tf32(float f) {
    uint32_t r;
    asm("cvt.rna.tf32.f32 %0, %1;" : "=r"(r) : "f"(f));
    return r;
}
__device__ __forceinline__ void mma_tf32(float* c, const uint32_t* a, const uint32_t* b) {
    asm("mma.sync.aligned.m16n8k8.row.col.f32.tf32.tf32.f32 "
        "{%0,%1,%2,%3}, {%4,%5,%6,%7}, {%8,%9}, {%0,%1,%2,%3};"
        : "+f"(c[0]), "+f"(c[1]), "+f"(c[2]), "+f"(c[3])
        : "r"(a[0]), "r"(a[1]), "r"(a[2]), "r"(a[3]), "r"(b[0]), "r"(b[1]));
}

// ---------------- tf32 tensor-core output GEMM -------------------------------
// C[M,Nc] = relu(bn(A)) @ B + bias, with M=NN, Nc=OUT_DIM, K=HD2=64 (full K in smem).
// BM=BN=128, 256 threads = 8 warps (2x4 warp grid, 64x32 warp tile).
__global__ __launch_bounds__(256, 2)
void k_gemm_tc(const float* __restrict__ A, const float* __restrict__ B,
               const float* __restrict__ bias, float* __restrict__ C,
               const float* __restrict__ gA, const float* __restrict__ beA,
               const float* __restrict__ SA, const float* __restrict__ QA,
               int M, int Nc) {
    __shared__ float As[128][68];   // 128 rows x 64 k (+4 pad; 68 mod 32 = 4)
    __shared__ float Bs[64][132];   // 64 k x 128 cols (+4 pad)
    __shared__ float aSc[HD2], aSh[HD2];
    int tid = threadIdx.x;
    int rowBase = blockIdx.y * 128;
    int colBase = blockIdx.x * 128;

    if (tid < HD2) {
        float mean = SA[tid] / (float)M;
        float var = QA[tid] / (float)M - mean * mean;
        float rstd = rsqrtf(var + EPSV);
        float scale = gA[tid] * rstd;
        aSc[tid] = scale;
        aSh[tid] = beA[tid] - mean * scale;
    }
    __syncthreads();

    // A tile fill with fused relu(bn): 128x64 = 2048 float4, 8 per thread
    #pragma unroll
    for (int l = 0; l < 8; l++) {
        int f = tid + l * 256;
        int r = f >> 4;            // 0..127
        int c = (f & 15) * 4;      // 0..60
        int gr = rowBase + r;
        float4 v = make_float4(0.f, 0.f, 0.f, 0.f);
        if (gr < M) {
            v = *(const float4*)(A + (size_t)gr * HD2 + c);
            v.x = fmaxf(fmaf(v.x, aSc[c + 0], aSh[c + 0]), 0.f);
            v.y = fmaxf(fmaf(v.y, aSc[c + 1], aSh[c + 1]), 0.f);
            v.z = fmaxf(fmaf(v.z, aSc[c + 2], aSh[c + 2]), 0.f);
            v.w = fmaxf(fmaf(v.w, aSc[c + 3], aSh[c + 3]), 0.f);
        }
        As[r][c] = v.x; As[r][c + 1] = v.y; As[r][c + 2] = v.z; As[r][c + 3] = v.w;
    }
    // B tile fill: 64 k-rows x 128 cols = 2048 float4, 8 per thread
    #pragma unroll
    for (int l = 0; l < 8; l++) {
        int f = tid + l * 256;
        int r = f >> 5;            // 0..63
        int c = (f & 31) * 4;      // 0..124
        int gc = colBase + c;
        float4 v = make_float4(0.f, 0.f, 0.f, 0.f);
        if (gc + 3 < Nc) v = *(const float4*)(B + (size_t)r * Nc + gc);
        Bs[r][c] = v.x; Bs[r][c + 1] = v.y; Bs[r][c + 2] = v.z; Bs[r][c + 3] = v.w;
    }
    __syncthreads();

    int warpId = tid >> 5;
    int lane = tid & 31;
    int g = lane >> 2;             // 0..7
    int t = lane & 3;              // 0..3
    int rowOff = (warpId >> 2) * 64;   // 0 or 64
    int colOff = (warpId & 3) * 32;    // 0,32,64,96

    float cacc[4][4][4] = {};      // [mtile][ntile][reg]

    #pragma unroll
    for (int ks = 0; ks < 8; ks++) {
        int kb = ks * 8;
        uint32_t af[4][4];
        #pragma unroll
        for (int mt = 0; mt < 4; mt++) {
            int r0 = rowOff + mt * 16 + g;
            af[mt][0] = f2tf32(As[r0][kb + t]);
            af[mt][1] = f2tf32(As[r0 + 8][kb + t]);
            af[mt][2] = f2tf32(As[r0][kb + t + 4]);
            af[mt][3] = f2tf32(As[r0 + 8][kb + t + 4]);
        }
        uint32_t bf[4][2];
        #pragma unroll
        for (int nt = 0; nt < 4; nt++) {
            int c0 = colOff + nt * 8 + g;
            bf[nt][0] = f2tf32(Bs[kb + t][c0]);
            bf[nt][1] = f2tf32(Bs[kb + t + 4][c0]);
        }
        #pragma unroll
        for (int mt = 0; mt < 4; mt++)
            #pragma unroll
            for (int nt = 0; nt < 4; nt++)
                mma_tf32(cacc[mt][nt], af[mt], bf[nt]);
    }

    // epilogue: scattered fragment writes with guards (+bias)
    #pragma unroll
    for (int mt = 0; mt < 4; mt++) {
        int row0 = rowBase + rowOff + mt * 16 + g;
        int row1 = row0 + 8;
        #pragma unroll
        for (int nt = 0; nt < 4; nt++) {
            int col = colBase + colOff + nt * 8 + 2 * t;
            const float* cc = cacc[mt][nt];
            if (row0 < M) {
                if (col < Nc)     C[(size_t)row0 * Nc + col]     = cc[0] + bias[col];
                if (col + 1 < Nc) C[(size_t)row0 * Nc + col + 1] = cc[1] + bias[col + 1];
            }
            if (row1 < M) {
                if (col < Nc)     C[(size_t)row1 * Nc + col]     = cc[2] + bias[col];
                if (col + 1 < Nc) C[(size_t)row1 * Nc + col + 1] = cc[3] + bias[col + 1];
            }
        }
    }
}

// ---------------- BN apply + ReLU, vectorized float4 (layer 1 only) ----------
__global__ __launch_bounds__(256)
void k_apply(const float* __restrict__ Y, const float* __restrict__ g,
             const float* __restrict__ be, const float* __restrict__ S,
             const float* __restrict__ Q, float* __restrict__ H,
             int M, int C) {
    __shared__ float4 sc4[32], sh4[32];
    int tid = threadIdx.x;
    int c4 = C >> 2;
    if (tid < c4) {
        float4 s4, h4;
        float* sp = (float*)&s4;
        float* hp = (float*)&h4;
        #pragma unroll
        for (int k = 0; k < 4; k++) {
            int col = tid * 4 + k;
            float mean = S[col] / (float)M;
            float var = Q[col] / (float)M - mean * mean;
            float rstd = rsqrtf(var + EPSV);
            float scale = g[col] * rstd;
            sp[k] = scale;
            hp[k] = be[col] - mean * scale;
        }
        sc4[tid] = s4; sh4[tid] = h4;
    }
    __syncthreads();
    int total = M * c4;
    int stride = gridDim.x * blockDim.x;
    int mask = c4 - 1;
    for (int idx = blockIdx.x * blockDim.x + tid; idx < total; idx += stride) {
        int j4 = idx & mask;
        float4 y = ((const float4*)Y)[idx];
        float4 sc = sc4[j4], sh = sh4[j4];
        float4 r;
        r.x = fmaxf(fmaf(y.x, sc.x, sh.x), 0.f);
        r.y = fmaxf(fmaf(y.y, sc.y, sh.y), 0.f);
        r.z = fmaxf(fmaf(y.z, sc.z, sh.z), 0.f);
        r.w = fmaxf(fmaf(y.w, sc.w, sh.w), 0.f);
        ((float4*)H)[idx] = r;
    }
}

// ---------------- column stats for O64 (final BN) ----------------------------
__global__ __launch_bounds__(256)
void k_stats64(const float* __restrict__ Y, float* __restrict__ S,
               float* __restrict__ Q, int M) {
    int col = threadIdx.x & 63;
    int rg = threadIdx.x >> 6;  // 0..3
    float s = 0.f, q = 0.f;
    for (int r = blockIdx.x * 4 + rg; r < M; r += gridDim.x * 4) {
        float v = Y[(size_t)r * HD2 + col];
        s += v; q += v * v;
    }
    atomicAdd(S + col, s);
    atomicAdd(Q + col, q);
}

// ---------------- CSR build: histogram -> scan -> scatter --------------------
__global__ void k_hist(const int* __restrict__ dst) {
    int t = blockIdx.x * blockDim.x + threadIdx.x;
    int stride = gridDim.x * blockDim.x;
    for (int e = t; e < EE; e += stride) atomicAdd(&g_deg[dst[e]], 1);
}

__global__ void k_scan() {  // one block, 1024 threads
    __shared__ int ss[1024];
    int t = threadIdx.x;
    const int CH = (NN + 1023) / 1024;
    int lo = t * CH;
    int hi = lo + CH; if (hi > NN) hi = NN;
    int loc = 0;
    for (int i = lo; i < hi; i++) loc += g_deg[i];
    ss[t] = loc;
    __syncthreads();
    for (int off = 1; off < 1024; off <<= 1) {
        int v = (t >= off) ? ss[t - off] : 0;
        __syncthreads();
        ss[t] += v;
        __syncthreads();
    }
    int run = ss[t] - loc;  // exclusive prefix
    for (int i = lo; i < hi; i++) {
        g_rowptr[i] = run;
        g_cursor[i] = run;
        run += g_deg[i];
    }
    if (t == 1023) g_rowptr[NN] = ss[1023];
}

__global__ void k_scatter(const int* __restrict__ src, const int* __restrict__ dst) {
    int t = blockIdx.x * blockDim.x + threadIdx.x;
    int stride = gridDim.x * blockDim.x;
    for (int e = t; e < EE; e += stride) {
        int d = dst[e];
        int p = atomicAdd(&g_cursor[d], 1);
        g_colidx[p] = src[e];
    }
}

// ---------------- 64d propagation hop: half-warp-per-dst gather-reduce -------
__global__ __launch_bounds__(256)
void k_hop64(int hop) {
    const float* __restrict__ cur = (hop & 1) ? g_PB : g_P;
    float* __restrict__ nxt       = (hop & 1) ? g_P : g_PB;
    int gid = blockIdx.x * blockDim.x + threadIdx.x;
    int d = gid >> 4;            // half-warp per destination node
    int lane = threadIdx.x & 15;
    if (d >= NN) return;
    float w = g_w[hop + 1];
    int s = g_rowptr[d];
    int e = g_rowptr[d + 1];
    float4 acc0 = make_float4(0.f, 0.f, 0.f, 0.f);
    float4 acc1 = make_float4(0.f, 0.f, 0.f, 0.f);
    float4 acc2 = make_float4(0.f, 0.f, 0.f, 0.f);
    float4 acc3 = make_float4(0.f, 0.f, 0.f, 0.f);
    int i = s;
    for (; i + 3 < e; i += 4) {
        int s0 = __ldg(&g_colidx[i]);
        int s1 = __ldg(&g_colidx[i + 1]);
        int s2 = __ldg(&g_colidx[i + 2]);
        int s3 = __ldg(&g_colidx[i + 3]);
        float4 v0 = *(const float4*)(cur + (size_t)s0 * HD2 + lane * 4);
        float4 v1 = *(const float4*)(cur + (size_t)s1 * HD2 + lane * 4);
        float4 v2 = *(const float4*)(cur + (size_t)s2 * HD2 + lane * 4);
        float4 v3 = *(const float4*)(cur + (size_t)s3 * HD2 + lane * 4);
        acc0.x += v0.x; acc0.y += v0.y; acc0.z += v0.z; acc0.w += v0.w;
        acc1.x += v1.x; acc1.y += v1.y; acc1.z += v1.z; acc1.w += v1.w;
        acc2.x += v2.x; acc2.y += v2.y; acc2.z += v2.z; acc2.w += v2.w;
        acc3.x += v3.x; acc3.y += v3.y; acc3.z += v3.z; acc3.w += v3.w;
    }
    for (; i < e; i++) {
        int s0 = __ldg(&g_colidx[i]);
        float4 v0 = *(const float4*)(cur + (size_t)s0 * HD2 + lane * 4);
        acc0.x += v0.x; acc0.y += v0.y; acc0.z += v0.z; acc0.w += v0.w;
    }
    float4 a = make_float4((acc0.x + acc1.x) + (acc2.x + acc3.x),
                           (acc0.y + acc1.y) + (acc2.y + acc3.y),
                           (acc0.z + acc1.z) + (acc2.z + acc3.z),
                           (acc0.w + acc1.w) + (acc2.w + acc3.w));
    size_t base = (size_t)d * HD2 + lane * 4;
    *(float4*)(nxt + base) = a;
    float4 o;
    if (hop == 0) {
        float w0 = g_w[0];
        float4 c = *(const float4*)(cur + base);
        o = make_float4(w0 * c.x, w0 * c.y, w0 * c.z, w0 * c.w);
    } else {
        o = *(float4*)(g_O64 + base);
    }
    o.x += w * a.x; o.y += w * a.y; o.z += w * a.z; o.w += w * a.w;
    *(float4*)(g_O64 + base) = o;
}

// ---------------- host launcher ----------------------------------------------
extern "C" void kernel_launch(void* const* d_in, const int* in_sizes, int n_in,
                              void* d_out, int out_size) {
    const float* x    = (const float*)d_in[0];
    const int*   ei   = (const int*)d_in[1];
    const float* W1   = (const float*)d_in[2];
    const float* g1   = (const float*)d_in[4];
    const float* be1  = (const float*)d_in[5];
    const float* W2   = (const float*)d_in[6];
    const float* g2   = (const float*)d_in[8];
    const float* be2  = (const float*)d_in[9];
    const float* att  = (const float*)d_in[10];
    const float* W3   = (const float*)d_in[11];
    const float* g3   = (const float*)d_in[13];
    const float* be3  = (const float*)d_in[14];
    const float* Wout = (const float*)d_in[15];
    const float* bout = (const float*)d_in[16];
    const int* srcp = ei;
    const int* dstp = ei + EE;
    float* out = (float*)d_out;

    float *Y1, *Y2, *H1, *P, *O64, *S1, *Q1, *S2, *Q2, *S3, *Q3;
    cudaGetSymbolAddress((void**)&Y1,  g_Y1);
    cudaGetSymbolAddress((void**)&Y2,  g_Y2);
    cudaGetSymbolAddress((void**)&H1,  g_H1);
    cudaGetSymbolAddress((void**)&P,   g_P);
    cudaGetSymbolAddress((void**)&O64, g_O64);
    cudaGetSymbolAddress((void**)&S1,  g_S1);
    cudaGetSymbolAddress((void**)&Q1,  g_Q1);
    cudaGetSymbolAddress((void**)&S2,  g_S2);
    cudaGetSymbolAddress((void**)&Q2,  g_Q2);
    cudaGetSymbolAddress((void**)&S3,  g_S3);
    cudaGetSymbolAddress((void**)&Q3,  g_Q3);

    const int MB = (NN + 127) / 128;  // 391 row-tiles

    k_init<<<200, 256>>>(att);

    // CSR by destination (independent of MLP; do it early)
    k_hist<<<1024, 256>>>(dstp);
    k_scan<<<1, 1024>>>();
    k_scatter<<<1024, 256>>>(srcp, dstp);

    // layer 1: Y1 = x @ W1 (stats fused); H1 = relu(bn1(Y1))
    k_gemm<false, false, true><<<dim3(2, MB), 256>>>(
        x, W1, nullptr, Y1, S1, Q1,
        nullptr, nullptr, nullptr, nullptr, nullptr, NN, HD, IN_DIM);
    k_apply<<<2048, 256>>>(Y1, g1, be1, S1, Q1, H1, NN, HD);

    // layer 2: Y2 = H1 @ W2 (stats fused)
    k_gemm<false, false, true><<<dim3(2, MB), 256>>>(
        H1, W2, nullptr, Y2, S2, Q2,
        nullptr, nullptr, nullptr, nullptr, nullptr, NN, HD, HD);

    // projection with fused apply: P = (relu(bn2(Y2)) + H1) @ W3
    k_gemm<true, true, false><<<dim3(1, MB), 256>>>(
        Y2, W3, nullptr, P, nullptr, nullptr,
        g2, be2, S2, Q2, H1, NN, HD2, HD);

    // K hops in 64d; weighted accumulation fused (hop 0 seeds O64 = w0*P)
    for (int h = 0; h < KHOPS; h++)
        k_hop64<<<(NN * 16 + 255) / 256, 256>>>(h);

    // output: out = relu(bn3(O64)) @ Wout + bout   [tf32 tensor cores]
    k_stats64<<<1024, 256>>>(O64, S3, Q3, NN);
    k_gemm_tc<<<dim3((OUT_DIM + 127) / 128, MB), 256>>>(
        O64, Wout, bout, out, g3, be3, S3, Q3, NN, OUT_DIM);
}